// round 13
// baseline (speedup 1.0000x reference)
#include <cuda_runtime.h>
#include <cuda_bf16.h>

// ---------------- problem-size capacities (fixed by the dataset) -------------
#define N_CAP 100000
#define E_CAP 3200000
#define F_IN  512
#define F_MID 16
#define STRIDE 96          // fixed bucket capacity per dst row (deg ~ Poisson(32))
#define NPB   256          // nodes per gemm1 block
#define KCH   16           // k-chunk staged in smem
#define XSTR  260          // xs node stride: 16B-aligned, 2-way STS conflicts only
#define NSPLIT 4
#define KQ    (F_IN / NSPLIT)   // 128 k per split

// ---------------- device scratch (accessed ONLY by symbol in device code) ----
__device__ __align__(16) int   g_cnt[N_CAP];            // per-row fill count = degree
__device__ __align__(16) float g_dis[N_CAP];            // (deg+1)^-1/2
__device__ __align__(16) int   g_bkt[N_CAP * STRIDE];   // fixed-stride CSR buckets
__device__ __align__(16) float g_part[NSPLIT][N_CAP * F_MID];  // split-K partials
__device__ __align__(16) float g_hs1[N_CAP * F_MID];    // dis ⊙ (x @ W1)
__device__ __align__(16) float g_hs2[N_CAP * F_MID];    // dis ⊙ (agg1 @ W2)

// packed f32x2 helpers (sm_103a: 2x-rate packed fp32 pipe)
#define FMA_F32X2(d, a, b, c) \
    asm("fma.rn.f32x2 %0, %1, %2, %3;" : "=l"(d) : "l"(a), "l"(b), "l"(c))
#define PACK2(d, f) \
    asm("mov.b64 %0, {%1, %1};" : "=l"(d) : "f"(f))

// ---------------- 1: zero counters ----------------
__global__ void k_zero(int N) {
    int i = blockIdx.x * blockDim.x + threadIdx.x;
    if (i < N) g_cnt[i] = 0;
}

// ---------------- 2: MERGED kernel: 4-way split-K gemm1 + fill ---------------
// blocks [0, g1b)        : partial h1 = x[:, ksplit] @ W1[ksplit, :] (unscaled)
// blocks [g1b, g1b+fillb): bucket fill, 8 edges/thread (atomic slot assignment)
__global__ __launch_bounds__(256, 5) void k_main(const float* __restrict__ x,
                                                 const float* __restrict__ w,
                                                 const int* __restrict__ ei,
                                                 int E, int N, int g1b) {
    __shared__ __align__(16) float ws[KQ * F_MID];     // 8 KB (quarter of W1)
    __shared__ __align__(16) float xs[KCH * XSTR];     // 16.6 KB

    if (blockIdx.x >= g1b) {
        // ---------------- fill branch, 8 edges/thread ----------------
        int t = (blockIdx.x - g1b) * blockDim.x + threadIdx.x;
        int e8 = t * 8;
        if (e8 + 7 < E) {
#pragma unroll
            for (int q = 0; q < 2; q++) {
                int4 s4 = *(const int4*)(ei + e8 + q * 4);
                int4 d4 = *(const int4*)(ei + E + e8 + q * 4);
                int slot;
                if ((unsigned)d4.x < (unsigned)N && (unsigned)s4.x < (unsigned)N) {
                    slot = atomicAdd(&g_cnt[d4.x], 1);
                    if (slot < STRIDE) g_bkt[d4.x * STRIDE + slot] = s4.x;
                }
                if ((unsigned)d4.y < (unsigned)N && (unsigned)s4.y < (unsigned)N) {
                    slot = atomicAdd(&g_cnt[d4.y], 1);
                    if (slot < STRIDE) g_bkt[d4.y * STRIDE + slot] = s4.y;
                }
                if ((unsigned)d4.z < (unsigned)N && (unsigned)s4.z < (unsigned)N) {
                    slot = atomicAdd(&g_cnt[d4.z], 1);
                    if (slot < STRIDE) g_bkt[d4.z * STRIDE + slot] = s4.z;
                }
                if ((unsigned)d4.w < (unsigned)N && (unsigned)s4.w < (unsigned)N) {
                    slot = atomicAdd(&g_cnt[d4.w], 1);
                    if (slot < STRIDE) g_bkt[d4.w * STRIDE + slot] = s4.w;
                }
            }
        } else {
            for (int e = e8; e < E; e++) {
                int s = ei[e];
                int d = ei[E + e];
                if ((unsigned)d < (unsigned)N && (unsigned)s < (unsigned)N) {
                    int slot = atomicAdd(&g_cnt[d], 1);
                    if (slot < STRIDE) g_bkt[d * STRIDE + slot] = s;
                }
            }
        }
        return;
    }

    // ---------------- split-K gemm1 branch -----------------------------------
    int split = blockIdx.x & (NSPLIT - 1);    // interleaved co-scheduling
    int nblk  = blockIdx.x >> 2;
    int kbase = split * KQ;
    float* hp = g_part[split];

    int t  = threadIdx.x;
    int n0 = nblk * NPB;
    int r  = t >> 2;     // staging row 0..63
    int c  = t & 3;      // staging col group
    int ng = t >> 2;     // node group (4 nodes)
    int jg = t & 3;      // feature group (4 features)

    // stage this split's quarter of W (read after first __syncthreads)
    for (int i = t; i < (KQ * F_MID) / 4; i += 256)
        ((float4*)ws)[i] = __ldg(&((const float4*)(w + kbase * F_MID))[i]);

    // prefetch chunk 0
    float4 buf[4];
#pragma unroll
    for (int p = 0; p < 4; p++) {
        int n = n0 + p * 64 + r;
        buf[p] = (n < N) ? __ldg((const float4*)(x + (size_t)n * F_IN + kbase + c * 4))
                         : make_float4(0.f, 0.f, 0.f, 0.f);
    }

    unsigned long long acc[4][2], zero;
    PACK2(zero, 0.0f);
#pragma unroll
    for (int i = 0; i < 4; i++) { acc[i][0] = zero; acc[i][1] = zero; }

    for (int chunk = 0; chunk < KQ / KCH; chunk++) {
        __syncthreads();
        // transposed STS (2-way conflicts with XSTR=260)
#pragma unroll
        for (int p = 0; p < 4; p++) {
            int row = p * 64 + r;
            xs[(c * 4 + 0) * XSTR + row] = buf[p].x;
            xs[(c * 4 + 1) * XSTR + row] = buf[p].y;
            xs[(c * 4 + 2) * XSTR + row] = buf[p].z;
            xs[(c * 4 + 3) * XSTR + row] = buf[p].w;
        }
        __syncthreads();

        // prefetch next chunk (overlaps compute)
        if (chunk + 1 < KQ / KCH) {
            int k0n = kbase + (chunk + 1) * KCH;
#pragma unroll
            for (int p = 0; p < 4; p++) {
                int n = n0 + p * 64 + r;
                buf[p] = (n < N) ? __ldg((const float4*)(x + (size_t)n * F_IN + k0n + c * 4))
                                 : make_float4(0.f, 0.f, 0.f, 0.f);
            }
        }

        int k0 = chunk * KCH;
#pragma unroll
        for (int k = 0; k < KCH; k++) {
            ulonglong2 wv = *(const ulonglong2*)(ws + (k0 + k) * 16 + jg * 4);
            float4 xv = *(const float4*)(xs + k * XSTR + ng * 4);
            unsigned long long xp0, xp1, xp2, xp3;
            PACK2(xp0, xv.x); PACK2(xp1, xv.y); PACK2(xp2, xv.z); PACK2(xp3, xv.w);
            FMA_F32X2(acc[0][0], xp0, wv.x, acc[0][0]);
            FMA_F32X2(acc[0][1], xp0, wv.y, acc[0][1]);
            FMA_F32X2(acc[1][0], xp1, wv.x, acc[1][0]);
            FMA_F32X2(acc[1][1], xp1, wv.y, acc[1][1]);
            FMA_F32X2(acc[2][0], xp2, wv.x, acc[2][0]);
            FMA_F32X2(acc[2][1], xp2, wv.y, acc[2][1]);
            FMA_F32X2(acc[3][0], xp3, wv.x, acc[3][0]);
            FMA_F32X2(acc[3][1], xp3, wv.y, acc[3][1]);
        }
    }

    // store UNSCALED partial (combined + scaled in k_finscale)
#pragma unroll
    for (int i = 0; i < 4; i++) {
        int n = n0 + ng * 4 + i;
        if (n < N) {
            ulonglong2 v; v.x = acc[i][0]; v.y = acc[i][1];
            *(ulonglong2*)(hp + (size_t)n * 16 + jg * 4) = v;
        }
    }
}

// ---------------- 3: combine split-K partials, compute dis, scale -----------
__global__ void k_finscale(int N) {
    int i = blockIdx.x * blockDim.x + threadIdx.x;
    int node = i >> 2;
    int f    = i & 3;
    if (node >= N) return;
    float dd = rsqrtf((float)(g_cnt[node] + 1));   // + self loop
    if (f == 0) g_dis[node] = dd;
    size_t off = (size_t)node * 16 + f * 4;
    float4 a = *(const float4*)(g_part[0] + off);
    float4 b = *(const float4*)(g_part[1] + off);
    float4 cc = *(const float4*)(g_part[2] + off);
    float4 e = *(const float4*)(g_part[3] + off);
    float4 v;
    v.x = dd * ((a.x + b.x) + (cc.x + e.x));
    v.y = dd * ((a.y + b.y) + (cc.y + e.y));
    v.z = dd * ((a.z + b.z) + (cc.z + e.z));
    v.w = dd * ((a.w + b.w) + (cc.w + e.w));
    *(float4*)(g_hs1 + off) = v;
}

// ---------------- 4/5: aggregation, 2 dst nodes per warp --------------------
// halfwarp h = lane>>4 owns node d = warp*2+h; within 16 lanes:
// sl = (lane>>2)&3 (4 edge slots), f = lane&3 (float4 feature group).
// layer 0: t[d] = dis[d]*(Σ hs1[s] + hs1[d]);  g_hs2[d] = dis[d]*(t[d] @ W2)
// layer 1: out[d] = dis[d]*(Σ hs2[s] + hs2[d])
__global__ __launch_bounds__(256) void k_agg(int layer, const float* __restrict__ w2,
                                             float* __restrict__ out, int N) {
    __shared__ float wt[256];
    if (layer == 0 && threadIdx.x < 256) wt[threadIdx.x] = w2[threadIdx.x];
    if (layer == 0) __syncthreads();

    int warp = (blockIdx.x * blockDim.x + threadIdx.x) >> 5;
    int lane = threadIdx.x & 31;
    int half = lane >> 4;
    int d    = warp * 2 + half;
    if (d >= N) return;

    const float* hs = (layer == 0) ? g_hs1 : g_hs2;

    int start = d * STRIDE;
    int cnt   = g_cnt[d];
    if (cnt > STRIDE) cnt = STRIDE;
    int sl = (lane >> 2) & 3;   // edge slot 0..3 within halfwarp
    int f  = lane & 3;          // feature group: floats [4f, 4f+4)

    float ax = 0.f, ay = 0.f, az = 0.f, aw = 0.f;

    int base = 0;
    // 8 edges per iteration per node: 2 independent L2 chains per lane
    for (; base + 8 <= cnt; base += 8) {
        int sA = __ldg(&g_bkt[start + base + sl]);
        int sB = __ldg(&g_bkt[start + base + 4 + sl]);
        float4 vA = __ldg((const float4*)(hs + (size_t)sA * 16 + f * 4));
        float4 vB = __ldg((const float4*)(hs + (size_t)sB * 16 + f * 4));
        ax += vA.x + vB.x; ay += vA.y + vB.y;
        az += vA.z + vB.z; aw += vA.w + vB.w;
    }
    for (; base < cnt; base += 4) {
        if (base + sl < cnt) {
            int s = __ldg(&g_bkt[start + base + sl]);
            float4 v = __ldg((const float4*)(hs + (size_t)s * 16 + f * 4));
            ax += v.x; ay += v.y; az += v.z; aw += v.w;
        }
    }
    // reduce across the 4 slots (xor 4, 8 stays within the 16-lane half)
#pragma unroll
    for (int off = 4; off <= 8; off <<= 1) {
        ax += __shfl_xor_sync(0xffffffffu, ax, off);
        ay += __shfl_xor_sync(0xffffffffu, ay, off);
        az += __shfl_xor_sync(0xffffffffu, az, off);
        aw += __shfl_xor_sync(0xffffffffu, aw, off);
    }

    // self loop (pre-scaled), then scale by dis[d]
    float4 sv = __ldg((const float4*)(hs + (size_t)d * 16 + f * 4));
    float dd = g_dis[d];
    float tx = dd * (ax + sv.x);
    float ty = dd * (ay + sv.y);
    float tz = dd * (az + sv.z);
    float tw = dd * (aw + sv.w);

    if (layer == 0) {
        // fused GEMM2: feature i of this node lives in component i&3 of
        // absolute lane (half<<4) + (i>>2). Each of the 16 lanes computes j.
        int j = lane & 15;
        int lb = half << 4;
        float h2 = 0.f;
#pragma unroll
        for (int i = 0; i < 16; i++) {
            float cc = ((i & 3) == 0) ? tx : ((i & 3) == 1) ? ty : ((i & 3) == 2) ? tz : tw;
            float ti = __shfl_sync(0xffffffffu, cc, lb + (i >> 2));
            h2 += ti * wt[i * 16 + j];
        }
        g_hs2[(size_t)d * 16 + j] = dd * h2;   // all 32 lanes: 128B per warp
    } else {
        if (sl == 0) {   // lanes {0..3} and {16..19} store float4 rows
            float4 o; o.x = tx; o.y = ty; o.z = tz; o.w = tw;
            *((float4*)(out + (size_t)d * 16 + f * 4)) = o;
        }
    }
}

// ---------------- launch ----------------
extern "C" void kernel_launch(void* const* d_in, const int* in_sizes, int n_in,
                              void* d_out, int out_size) {
    const float* x   = (const float*)d_in[0];
    const int*   ei  = (const int*)d_in[1];     // int32 (JAX x64 disabled)
    const float* w1  = (const float*)d_in[2];
    const float* w2  = (const float*)d_in[3];
    float*       out = (float*)d_out;

    int N = in_sizes[0] / F_IN;   // 100000
    int E = in_sizes[1] / 2;      // 3200000
    int E8 = (E + 7) / 8;

    int g1b   = NSPLIT * ((N + NPB - 1) / NPB);  // 1564 split-K gemm1 blocks
    int fillb = (E8 + 255) / 256;                // 1563 fill blocks

    k_zero    <<<(N + 255) / 256, 256>>>(N);
    k_main    <<<g1b + fillb, 256>>>(x, w1, ei, E, N, g1b);   // overlapped fill+gemm1
    k_finscale<<<(N * 4 + 255) / 256, 256>>>(N);

    int aggw = (N + 1) / 2;                  // warps (2 nodes each)
    k_agg<<<(aggw * 32 + 255) / 256, 256>>>(0, w2, out, N);
    k_agg<<<(aggw * 32 + 255) / 256, 256>>>(1, w2, out, N);
}

// round 14
// speedup vs baseline: 1.0382x; 1.0382x over previous
#include <cuda_runtime.h>
#include <cuda_bf16.h>

// ---------------- problem-size capacities (fixed by the dataset) -------------
#define N_CAP 100000
#define E_CAP 3200000
#define F_IN  512
#define F_MID 16
#define STRIDE 96          // fixed bucket capacity per dst row (deg ~ Poisson(32))
#define NPB   256          // nodes per gemm1 block
#define KCH   16           // k-chunk staged in smem
#define XSTR  260          // xs node stride: 16B-aligned, 2-way STS conflicts only
#define KHALF (F_IN / 2)   // 256 k per split

// ---------------- device scratch (accessed ONLY by symbol in device code) ----
__device__ __align__(16) int   g_cnt[N_CAP];            // per-row fill count = degree
__device__ __align__(16) float g_dis[N_CAP];            // (deg+1)^-1/2
__device__ __align__(16) int   g_bkt[N_CAP * STRIDE];   // fixed-stride CSR buckets
__device__ __align__(16) float g_p0[N_CAP * F_MID];     // split-K partial 0
__device__ __align__(16) float g_p1[N_CAP * F_MID];     // split-K partial 1
__device__ __align__(16) float g_hs1[N_CAP * F_MID];    // dis ⊙ (x @ W1)
__device__ __align__(16) float g_hs2[N_CAP * F_MID];    // dis ⊙ (agg1 @ W2)

// packed f32x2 helpers (sm_103a: 2x-rate packed fp32 pipe)
#define FMA_F32X2(d, a, b, c) \
    asm("fma.rn.f32x2 %0, %1, %2, %3;" : "=l"(d) : "l"(a), "l"(b), "l"(c))
#define PACK2(d, f) \
    asm("mov.b64 %0, {%1, %1};" : "=l"(d) : "f"(f))

// ---------------- 1: zero counters ----------------
__global__ void k_zero(int N) {
    int i = blockIdx.x * blockDim.x + threadIdx.x;
    if (i < N) g_cnt[i] = 0;
}

// ---------------- 2: MERGED kernel, uniformly interleaved ---------------------
// bid % 3 == 0 -> split-K gemm1 block (id = bid/3, 782 total)
// else         -> fill block (id = (bid/3)*2 + bid%3 - 1, 1564 total)
// Uniform mixing keeps FMA-bound gemm and L2-atomic-bound fill co-resident on
// every SM for the whole kernel (R12 scheduled all gemm first).
__global__ __launch_bounds__(256) void k_main(const float* __restrict__ x,
                                              const float* __restrict__ w,
                                              const int* __restrict__ ei,
                                              int E, int N) {
    __shared__ __align__(16) float ws[KHALF * F_MID];  // 16 KB (half of W1)
    __shared__ __align__(16) float xs[KCH * XSTR];     // 16.6 KB

    int bmod = blockIdx.x % 3;
    int bdiv = blockIdx.x / 3;

    if (bmod != 0) {
        // ---------------- fill branch, 8 edges/thread ----------------
        int fb = bdiv * 2 + (bmod - 1);
        int t = fb * blockDim.x + threadIdx.x;
        int e8 = t * 8;
        if (e8 + 7 < E) {
#pragma unroll
            for (int q = 0; q < 2; q++) {
                int4 s4 = *(const int4*)(ei + e8 + q * 4);
                int4 d4 = *(const int4*)(ei + E + e8 + q * 4);
                int slot;
                if ((unsigned)d4.x < (unsigned)N && (unsigned)s4.x < (unsigned)N) {
                    slot = atomicAdd(&g_cnt[d4.x], 1);
                    if (slot < STRIDE) g_bkt[d4.x * STRIDE + slot] = s4.x;
                }
                if ((unsigned)d4.y < (unsigned)N && (unsigned)s4.y < (unsigned)N) {
                    slot = atomicAdd(&g_cnt[d4.y], 1);
                    if (slot < STRIDE) g_bkt[d4.y * STRIDE + slot] = s4.y;
                }
                if ((unsigned)d4.z < (unsigned)N && (unsigned)s4.z < (unsigned)N) {
                    slot = atomicAdd(&g_cnt[d4.z], 1);
                    if (slot < STRIDE) g_bkt[d4.z * STRIDE + slot] = s4.z;
                }
                if ((unsigned)d4.w < (unsigned)N && (unsigned)s4.w < (unsigned)N) {
                    slot = atomicAdd(&g_cnt[d4.w], 1);
                    if (slot < STRIDE) g_bkt[d4.w * STRIDE + slot] = s4.w;
                }
            }
        } else if (e8 < E) {
            for (int e = e8; e < E; e++) {
                int s = ei[e];
                int d = ei[E + e];
                if ((unsigned)d < (unsigned)N && (unsigned)s < (unsigned)N) {
                    int slot = atomicAdd(&g_cnt[d], 1);
                    if (slot < STRIDE) g_bkt[d * STRIDE + slot] = s;
                }
            }
        }
        return;
    }

    // ---------------- split-K gemm1 branch (R12 config) ----------------------
    int split = bdiv & 1;
    int nblk  = bdiv >> 1;
    int kbase = split * KHALF;
    float* hp = split ? g_p1 : g_p0;

    int t  = threadIdx.x;
    int n0 = nblk * NPB;
    int r  = t >> 2;     // staging row 0..63
    int c  = t & 3;      // staging col group
    int ng = t >> 2;     // node group (4 nodes)
    int jg = t & 3;      // feature group (4 features)

    // stage this split's half of W (read after first __syncthreads)
    for (int i = t; i < (KHALF * F_MID) / 4; i += 256)
        ((float4*)ws)[i] = __ldg(&((const float4*)(w + kbase * F_MID))[i]);

    // prefetch chunk 0
    float4 buf[4];
#pragma unroll
    for (int p = 0; p < 4; p++) {
        int n = n0 + p * 64 + r;
        buf[p] = (n < N) ? __ldg((const float4*)(x + (size_t)n * F_IN + kbase + c * 4))
                         : make_float4(0.f, 0.f, 0.f, 0.f);
    }

    unsigned long long acc[4][2], zero;
    PACK2(zero, 0.0f);
#pragma unroll
    for (int i = 0; i < 4; i++) { acc[i][0] = zero; acc[i][1] = zero; }

    for (int chunk = 0; chunk < KHALF / KCH; chunk++) {
        __syncthreads();
        // transposed STS (2-way conflicts with XSTR=260)
#pragma unroll
        for (int p = 0; p < 4; p++) {
            int row = p * 64 + r;
            xs[(c * 4 + 0) * XSTR + row] = buf[p].x;
            xs[(c * 4 + 1) * XSTR + row] = buf[p].y;
            xs[(c * 4 + 2) * XSTR + row] = buf[p].z;
            xs[(c * 4 + 3) * XSTR + row] = buf[p].w;
        }
        __syncthreads();

        // prefetch next chunk (overlaps compute)
        if (chunk + 1 < KHALF / KCH) {
            int k0n = kbase + (chunk + 1) * KCH;
#pragma unroll
            for (int p = 0; p < 4; p++) {
                int n = n0 + p * 64 + r;
                buf[p] = (n < N) ? __ldg((const float4*)(x + (size_t)n * F_IN + k0n + c * 4))
                                 : make_float4(0.f, 0.f, 0.f, 0.f);
            }
        }

        int k0 = chunk * KCH;
#pragma unroll
        for (int k = 0; k < KCH; k++) {
            ulonglong2 wv = *(const ulonglong2*)(ws + (k0 + k) * 16 + jg * 4);
            float4 xv = *(const float4*)(xs + k * XSTR + ng * 4);
            unsigned long long xp0, xp1, xp2, xp3;
            PACK2(xp0, xv.x); PACK2(xp1, xv.y); PACK2(xp2, xv.z); PACK2(xp3, xv.w);
            FMA_F32X2(acc[0][0], xp0, wv.x, acc[0][0]);
            FMA_F32X2(acc[0][1], xp0, wv.y, acc[0][1]);
            FMA_F32X2(acc[1][0], xp1, wv.x, acc[1][0]);
            FMA_F32X2(acc[1][1], xp1, wv.y, acc[1][1]);
            FMA_F32X2(acc[2][0], xp2, wv.x, acc[2][0]);
            FMA_F32X2(acc[2][1], xp2, wv.y, acc[2][1]);
            FMA_F32X2(acc[3][0], xp3, wv.x, acc[3][0]);
            FMA_F32X2(acc[3][1], xp3, wv.y, acc[3][1]);
        }
    }

    // store UNSCALED partial (combined + scaled in k_finscale)
#pragma unroll
    for (int i = 0; i < 4; i++) {
        int n = n0 + ng * 4 + i;
        if (n < N) {
            ulonglong2 v; v.x = acc[i][0]; v.y = acc[i][1];
            *(ulonglong2*)(hp + (size_t)n * 16 + jg * 4) = v;
        }
    }
}

// ---------------- 3: combine split-K partials, compute dis, scale -----------
__global__ void k_finscale(int N) {
    int i = blockIdx.x * blockDim.x + threadIdx.x;
    int node = i >> 2;
    int f    = i & 3;
    if (node >= N) return;
    float dd = rsqrtf((float)(g_cnt[node] + 1));   // + self loop
    if (f == 0) g_dis[node] = dd;
    size_t off = (size_t)node * 16 + f * 4;
    float4 a = *(const float4*)(g_p0 + off);
    float4 b = *(const float4*)(g_p1 + off);
    float4 v;
    v.x = dd * (a.x + b.x);
    v.y = dd * (a.y + b.y);
    v.z = dd * (a.z + b.z);
    v.w = dd * (a.w + b.w);
    *(float4*)(g_hs1 + off) = v;
}

// ---------------- 4/5: aggregation, 2 dst nodes per warp, idx-pipelined ------
// halfwarp h = lane>>4 owns node d = warp*2+h; within 16 lanes:
// sl = (lane>>2)&3 (4 edge slots), f = lane&3 (float4 feature group).
// Bucket indices for iteration i+1 are loaded before the row gathers of
// iteration i issue, overlapping the idx->row dependent chains.
__global__ __launch_bounds__(256) void k_agg(int layer, const float* __restrict__ w2,
                                             float* __restrict__ out, int N) {
    __shared__ float wt[256];
    if (layer == 0 && threadIdx.x < 256) wt[threadIdx.x] = w2[threadIdx.x];
    if (layer == 0) __syncthreads();

    int warp = (blockIdx.x * blockDim.x + threadIdx.x) >> 5;
    int lane = threadIdx.x & 31;
    int half = lane >> 4;
    int d    = warp * 2 + half;
    if (d >= N) return;

    const float* hs = (layer == 0) ? g_hs1 : g_hs2;

    int start = d * STRIDE;
    int cnt   = g_cnt[d];
    if (cnt > STRIDE) cnt = STRIDE;
    int sl = (lane >> 2) & 3;   // edge slot 0..3 within halfwarp
    int f  = lane & 3;          // feature group: floats [4f, 4f+4)

    float ax = 0.f, ay = 0.f, az = 0.f, aw = 0.f;

    int base = 0;
    int sA = 0, sB = 0;
    if (base + 8 <= cnt) {              // preload iteration 0 indices
        sA = __ldg(&g_bkt[start + sl]);
        sB = __ldg(&g_bkt[start + 4 + sl]);
    }
    for (; base + 8 <= cnt; base += 8) {
        int nA = sA, nB = sB;
        if (base + 16 <= cnt) {         // preload next indices BEFORE gathers
            sA = __ldg(&g_bkt[start + base + 8 + sl]);
            sB = __ldg(&g_bkt[start + base + 12 + sl]);
        }
        float4 vA = __ldg((const float4*)(hs + (size_t)nA * 16 + f * 4));
        float4 vB = __ldg((const float4*)(hs + (size_t)nB * 16 + f * 4));
        ax += vA.x + vB.x; ay += vA.y + vB.y;
        az += vA.z + vB.z; aw += vA.w + vB.w;
    }
    for (; base < cnt; base += 4) {
        if (base + sl < cnt) {
            int s = __ldg(&g_bkt[start + base + sl]);
            float4 v = __ldg((const float4*)(hs + (size_t)s * 16 + f * 4));
            ax += v.x; ay += v.y; az += v.z; aw += v.w;
        }
    }
    // reduce across the 4 slots (xor 4, 8 stays within the 16-lane half)
#pragma unroll
    for (int off = 4; off <= 8; off <<= 1) {
        ax += __shfl_xor_sync(0xffffffffu, ax, off);
        ay += __shfl_xor_sync(0xffffffffu, ay, off);
        az += __shfl_xor_sync(0xffffffffu, az, off);
        aw += __shfl_xor_sync(0xffffffffu, aw, off);
    }

    // self loop (pre-scaled), then scale by dis[d]
    float4 sv = __ldg((const float4*)(hs + (size_t)d * 16 + f * 4));
    float dd = g_dis[d];
    float tx = dd * (ax + sv.x);
    float ty = dd * (ay + sv.y);
    float tz = dd * (az + sv.z);
    float tw = dd * (aw + sv.w);

    if (layer == 0) {
        // fused GEMM2: feature i of this node lives in component i&3 of
        // absolute lane (half<<4) + (i>>2). Each of the 16 lanes computes j.
        int j = lane & 15;
        int lb = half << 4;
        float h2 = 0.f;
#pragma unroll
        for (int i = 0; i < 16; i++) {
            float cc = ((i & 3) == 0) ? tx : ((i & 3) == 1) ? ty : ((i & 3) == 2) ? tz : tw;
            float ti = __shfl_sync(0xffffffffu, cc, lb + (i >> 2));
            h2 += ti * wt[i * 16 + j];
        }
        g_hs2[(size_t)d * 16 + j] = dd * h2;   // all 32 lanes: 128B per warp
    } else {
        if (sl == 0) {   // lanes {0..3} and {16..19} store float4 rows
            float4 o; o.x = tx; o.y = ty; o.z = tz; o.w = tw;
            *((float4*)(out + (size_t)d * 16 + f * 4)) = o;
        }
    }
}

// ---------------- launch ----------------
extern "C" void kernel_launch(void* const* d_in, const int* in_sizes, int n_in,
                              void* d_out, int out_size) {
    const float* x   = (const float*)d_in[0];
    const int*   ei  = (const int*)d_in[1];     // int32 (JAX x64 disabled)
    const float* w1  = (const float*)d_in[2];
    const float* w2  = (const float*)d_in[3];
    float*       out = (float*)d_out;

    int N = in_sizes[0] / F_IN;   // 100000
    int E = in_sizes[1] / 2;      // 3200000

    int g1b = 2 * ((N + NPB - 1) / NPB);    // 782 gemm blocks; fill = 2*g1b = 1564
    // (1564 fill blocks x 256 threads x 8 edges = 3.2M+ covers E; guarded inside)

    k_zero    <<<(N + 255) / 256, 256>>>(N);
    k_main    <<<3 * g1b, 256>>>(x, w1, ei, E, N);        // interleaved fill+gemm1
    k_finscale<<<(N * 4 + 255) / 256, 256>>>(N);

    int aggw = (N + 1) / 2;                  // warps (2 nodes each)
    k_agg<<<(aggw * 32 + 255) / 256, 256>>>(0, w2, out, N);
    k_agg<<<(aggw * 32 + 255) / 256, 256>>>(1, w2, out, N);
}

// round 15
// speedup vs baseline: 1.0926x; 1.0525x over previous
#include <cuda_runtime.h>
#include <cuda_bf16.h>

// ---------------- problem-size capacities (fixed by the dataset) -------------
#define N_CAP 100000
#define E_CAP 3200000
#define F_IN  512
#define F_MID 16
#define STRIDE 96          // fixed bucket capacity per dst row (deg ~ Poisson(32))
#define NPB   256          // nodes per gemm1 block
#define KCH   16           // k-chunk staged in smem
#define XSTR  260          // xs node stride: 16B-aligned, 2-way STS conflicts only
#define KHALF (F_IN / 2)   // 256 k per split

// ---------------- device scratch (accessed ONLY by symbol in device code) ----
// NOTE: g_cnt relies on (a) zero-initialization of device globals at module
// load, (b) k_agg(layer=1) resetting it to zero after use every call, so the
// zero invariant holds across graph replays without a dedicated zeroing kernel.
__device__ __align__(16) int   g_cnt[N_CAP];            // per-row fill count = degree
__device__ __align__(16) float g_dis[N_CAP];            // (deg+1)^-1/2
__device__ __align__(16) int   g_bkt[N_CAP * STRIDE];   // fixed-stride CSR buckets
__device__ __align__(16) float g_p0[N_CAP * F_MID];     // split-K partial 0
__device__ __align__(16) float g_p1[N_CAP * F_MID];     // split-K partial 1
__device__ __align__(16) float g_hs1[N_CAP * F_MID];    // dis ⊙ (x @ W1)
__device__ __align__(16) float g_hs2[N_CAP * F_MID];    // dis ⊙ (agg1 @ W2)

// packed f32x2 helpers (sm_103a: 2x-rate packed fp32 pipe)
#define FMA_F32X2(d, a, b, c) \
    asm("fma.rn.f32x2 %0, %1, %2, %3;" : "=l"(d) : "l"(a), "l"(b), "l"(c))
#define PACK2(d, f) \
    asm("mov.b64 %0, {%1, %1};" : "=l"(d) : "f"(f))

// ---------------- 1: MERGED kernel: split-K gemm1 blocks then fill blocks ----
// blocks [0, g1b)        : partial h1 = x[:, ksplit] @ W1[ksplit, :] (unscaled)
// blocks [g1b, g1b+fillb): bucket fill, 8 edges/thread
// gemm blocks scheduled FIRST (longest-job-first: fill backfills behind them).
__global__ __launch_bounds__(256) void k_main(const float* __restrict__ x,
                                              const float* __restrict__ w,
                                              const int* __restrict__ ei,
                                              int E, int N, int g1b) {
    __shared__ __align__(16) float ws[KHALF * F_MID];  // 16 KB (half of W1)
    __shared__ __align__(16) float xs[KCH * XSTR];     // 16.6 KB

    if (blockIdx.x >= g1b) {
        // ---------------- fill branch, 8 edges/thread ----------------
        int t = (blockIdx.x - g1b) * blockDim.x + threadIdx.x;
        int e8 = t * 8;
        if (e8 + 7 < E) {
#pragma unroll
            for (int q = 0; q < 2; q++) {
                int4 s4 = *(const int4*)(ei + e8 + q * 4);
                int4 d4 = *(const int4*)(ei + E + e8 + q * 4);
                int slot;
                if ((unsigned)d4.x < (unsigned)N && (unsigned)s4.x < (unsigned)N) {
                    slot = atomicAdd(&g_cnt[d4.x], 1);
                    if (slot < STRIDE) g_bkt[d4.x * STRIDE + slot] = s4.x;
                }
                if ((unsigned)d4.y < (unsigned)N && (unsigned)s4.y < (unsigned)N) {
                    slot = atomicAdd(&g_cnt[d4.y], 1);
                    if (slot < STRIDE) g_bkt[d4.y * STRIDE + slot] = s4.y;
                }
                if ((unsigned)d4.z < (unsigned)N && (unsigned)s4.z < (unsigned)N) {
                    slot = atomicAdd(&g_cnt[d4.z], 1);
                    if (slot < STRIDE) g_bkt[d4.z * STRIDE + slot] = s4.z;
                }
                if ((unsigned)d4.w < (unsigned)N && (unsigned)s4.w < (unsigned)N) {
                    slot = atomicAdd(&g_cnt[d4.w], 1);
                    if (slot < STRIDE) g_bkt[d4.w * STRIDE + slot] = s4.w;
                }
            }
        } else if (e8 < E) {
            for (int e = e8; e < E; e++) {
                int s = ei[e];
                int d = ei[E + e];
                if ((unsigned)d < (unsigned)N && (unsigned)s < (unsigned)N) {
                    int slot = atomicAdd(&g_cnt[d], 1);
                    if (slot < STRIDE) g_bkt[d * STRIDE + slot] = s;
                }
            }
        }
        return;
    }

    // ---------------- split-K gemm1 branch -----------------------------------
    int split = blockIdx.x & 1;               // interleaved split co-scheduling
    int nblk  = blockIdx.x >> 1;
    int kbase = split * KHALF;
    float* hp = split ? g_p1 : g_p0;

    int t  = threadIdx.x;
    int n0 = nblk * NPB;
    int r  = t >> 2;     // staging row 0..63
    int c  = t & 3;      // staging col group
    int ng = t >> 2;     // node group (4 nodes)
    int jg = t & 3;      // feature group (4 features)

    // stage this split's half of W (read after first __syncthreads)
    for (int i = t; i < (KHALF * F_MID) / 4; i += 256)
        ((float4*)ws)[i] = __ldg(&((const float4*)(w + kbase * F_MID))[i]);

    // prefetch chunk 0
    float4 buf[4];
#pragma unroll
    for (int p = 0; p < 4; p++) {
        int n = n0 + p * 64 + r;
        buf[p] = (n < N) ? __ldg((const float4*)(x + (size_t)n * F_IN + kbase + c * 4))
                         : make_float4(0.f, 0.f, 0.f, 0.f);
    }

    unsigned long long acc[4][2], zero;
    PACK2(zero, 0.0f);
#pragma unroll
    for (int i = 0; i < 4; i++) { acc[i][0] = zero; acc[i][1] = zero; }

    for (int chunk = 0; chunk < KHALF / KCH; chunk++) {
        __syncthreads();
        // transposed STS (2-way conflicts with XSTR=260)
#pragma unroll
        for (int p = 0; p < 4; p++) {
            int row = p * 64 + r;
            xs[(c * 4 + 0) * XSTR + row] = buf[p].x;
            xs[(c * 4 + 1) * XSTR + row] = buf[p].y;
            xs[(c * 4 + 2) * XSTR + row] = buf[p].z;
            xs[(c * 4 + 3) * XSTR + row] = buf[p].w;
        }
        __syncthreads();

        // prefetch next chunk (overlaps compute)
        if (chunk + 1 < KHALF / KCH) {
            int k0n = kbase + (chunk + 1) * KCH;
#pragma unroll
            for (int p = 0; p < 4; p++) {
                int n = n0 + p * 64 + r;
                buf[p] = (n < N) ? __ldg((const float4*)(x + (size_t)n * F_IN + k0n + c * 4))
                                 : make_float4(0.f, 0.f, 0.f, 0.f);
            }
        }

        int k0 = chunk * KCH;
#pragma unroll
        for (int k = 0; k < KCH; k++) {
            ulonglong2 wv = *(const ulonglong2*)(ws + (k0 + k) * 16 + jg * 4);
            float4 xv = *(const float4*)(xs + k * XSTR + ng * 4);
            unsigned long long xp0, xp1, xp2, xp3;
            PACK2(xp0, xv.x); PACK2(xp1, xv.y); PACK2(xp2, xv.z); PACK2(xp3, xv.w);
            FMA_F32X2(acc[0][0], xp0, wv.x, acc[0][0]);
            FMA_F32X2(acc[0][1], xp0, wv.y, acc[0][1]);
            FMA_F32X2(acc[1][0], xp1, wv.x, acc[1][0]);
            FMA_F32X2(acc[1][1], xp1, wv.y, acc[1][1]);
            FMA_F32X2(acc[2][0], xp2, wv.x, acc[2][0]);
            FMA_F32X2(acc[2][1], xp2, wv.y, acc[2][1]);
            FMA_F32X2(acc[3][0], xp3, wv.x, acc[3][0]);
            FMA_F32X2(acc[3][1], xp3, wv.y, acc[3][1]);
        }
    }

    // store UNSCALED partial (combined + scaled in k_finscale)
#pragma unroll
    for (int i = 0; i < 4; i++) {
        int n = n0 + ng * 4 + i;
        if (n < N) {
            ulonglong2 v; v.x = acc[i][0]; v.y = acc[i][1];
            *(ulonglong2*)(hp + (size_t)n * 16 + jg * 4) = v;
        }
    }
}

// ---------------- 2: combine split-K partials, compute dis, scale -----------
__global__ void k_finscale(int N) {
    int i = blockIdx.x * blockDim.x + threadIdx.x;
    int node = i >> 2;
    int f    = i & 3;
    if (node >= N) return;
    float dd = rsqrtf((float)(g_cnt[node] + 1));   // + self loop
    if (f == 0) g_dis[node] = dd;
    size_t off = (size_t)node * 16 + f * 4;
    float4 a = *(const float4*)(g_p0 + off);
    float4 b = *(const float4*)(g_p1 + off);
    float4 v;
    v.x = dd * (a.x + b.x);
    v.y = dd * (a.y + b.y);
    v.z = dd * (a.z + b.z);
    v.w = dd * (a.w + b.w);
    *(float4*)(g_hs1 + off) = v;
}

// ---------------- 3/4: aggregation, 2 dst nodes per warp, idx-pipelined ------
// halfwarp h = lane>>4 owns node d = warp*2+h; within 16 lanes:
// sl = (lane>>2)&3 (4 edge slots), f = lane&3 (float4 feature group).
// Main loop: 16 edges/iter (4 independent row-gather chains) with next-iter
// index prefetch. layer 1 resets g_cnt[d]=0 after use (replaces k_zero).
__global__ __launch_bounds__(256) void k_agg(int layer, const float* __restrict__ w2,
                                             float* __restrict__ out, int N) {
    __shared__ float wt[256];
    if (layer == 0 && threadIdx.x < 256) wt[threadIdx.x] = w2[threadIdx.x];
    if (layer == 0) __syncthreads();

    int warp = (blockIdx.x * blockDim.x + threadIdx.x) >> 5;
    int lane = threadIdx.x & 31;
    int half = lane >> 4;
    int d    = warp * 2 + half;
    if (d >= N) return;

    const float* hs = (layer == 0) ? g_hs1 : g_hs2;

    int start = d * STRIDE;
    int cnt   = g_cnt[d];
    if (layer == 1 && lane == (half << 4)) g_cnt[d] = 0;   // restore zero invariant
    if (cnt > STRIDE) cnt = STRIDE;
    int sl = (lane >> 2) & 3;   // edge slot 0..3 within halfwarp
    int f  = lane & 3;          // feature group: floats [4f, 4f+4)

    float ax = 0.f, ay = 0.f, az = 0.f, aw = 0.f;

    int base = 0;
    int iA = 0, iB = 0, iC = 0, iD = 0;
    if (base + 16 <= cnt) {                 // preload iteration 0 indices
        iA = __ldg(&g_bkt[start + sl]);
        iB = __ldg(&g_bkt[start + 4 + sl]);
        iC = __ldg(&g_bkt[start + 8 + sl]);
        iD = __ldg(&g_bkt[start + 12 + sl]);
    }
    // 16 edges per iteration per node: 4 independent L2 chains per lane
    for (; base + 16 <= cnt; base += 16) {
        int nA = iA, nB = iB, nC = iC, nD = iD;
        if (base + 32 <= cnt) {             // prefetch next indices
            iA = __ldg(&g_bkt[start + base + 16 + sl]);
            iB = __ldg(&g_bkt[start + base + 20 + sl]);
            iC = __ldg(&g_bkt[start + base + 24 + sl]);
            iD = __ldg(&g_bkt[start + base + 28 + sl]);
        }
        float4 vA = __ldg((const float4*)(hs + (size_t)nA * 16 + f * 4));
        float4 vB = __ldg((const float4*)(hs + (size_t)nB * 16 + f * 4));
        float4 vC = __ldg((const float4*)(hs + (size_t)nC * 16 + f * 4));
        float4 vD = __ldg((const float4*)(hs + (size_t)nD * 16 + f * 4));
        ax += (vA.x + vB.x) + (vC.x + vD.x);
        ay += (vA.y + vB.y) + (vC.y + vD.y);
        az += (vA.z + vB.z) + (vC.z + vD.z);
        aw += (vA.w + vB.w) + (vC.w + vD.w);
    }
    for (; base + 8 <= cnt; base += 8) {
        int sA = __ldg(&g_bkt[start + base + sl]);
        int sB = __ldg(&g_bkt[start + base + 4 + sl]);
        float4 vA = __ldg((const float4*)(hs + (size_t)sA * 16 + f * 4));
        float4 vB = __ldg((const float4*)(hs + (size_t)sB * 16 + f * 4));
        ax += vA.x + vB.x; ay += vA.y + vB.y;
        az += vA.z + vB.z; aw += vA.w + vB.w;
    }
    for (; base < cnt; base += 4) {
        if (base + sl < cnt) {
            int s = __ldg(&g_bkt[start + base + sl]);
            float4 v = __ldg((const float4*)(hs + (size_t)s * 16 + f * 4));
            ax += v.x; ay += v.y; az += v.z; aw += v.w;
        }
    }
    // reduce across the 4 slots (xor 4, 8 stays within the 16-lane half)
#pragma unroll
    for (int off = 4; off <= 8; off <<= 1) {
        ax += __shfl_xor_sync(0xffffffffu, ax, off);
        ay += __shfl_xor_sync(0xffffffffu, ay, off);
        az += __shfl_xor_sync(0xffffffffu, az, off);
        aw += __shfl_xor_sync(0xffffffffu, aw, off);
    }

    // self loop (pre-scaled), then scale by dis[d]
    float4 sv = __ldg((const float4*)(hs + (size_t)d * 16 + f * 4));
    float dd = g_dis[d];
    float tx = dd * (ax + sv.x);
    float ty = dd * (ay + sv.y);
    float tz = dd * (az + sv.z);
    float tw = dd * (aw + sv.w);

    if (layer == 0) {
        // fused GEMM2: feature i of this node lives in component i&3 of
        // absolute lane (half<<4) + (i>>2). Each of the 16 lanes computes j.
        int j = lane & 15;
        int lb = half << 4;
        float h2 = 0.f;
#pragma unroll
        for (int i = 0; i < 16; i++) {
            float cc = ((i & 3) == 0) ? tx : ((i & 3) == 1) ? ty : ((i & 3) == 2) ? tz : tw;
            float ti = __shfl_sync(0xffffffffu, cc, lb + (i >> 2));
            h2 += ti * wt[i * 16 + j];
        }
        g_hs2[(size_t)d * 16 + j] = dd * h2;   // all 32 lanes: 128B per warp
    } else {
        if (sl == 0) {   // lanes {0..3} and {16..19} store float4 rows
            float4 o; o.x = tx; o.y = ty; o.z = tz; o.w = tw;
            *((float4*)(out + (size_t)d * 16 + f * 4)) = o;
        }
    }
}

// ---------------- launch ----------------
extern "C" void kernel_launch(void* const* d_in, const int* in_sizes, int n_in,
                              void* d_out, int out_size) {
    const float* x   = (const float*)d_in[0];
    const int*   ei  = (const int*)d_in[1];     // int32 (JAX x64 disabled)
    const float* w1  = (const float*)d_in[2];
    const float* w2  = (const float*)d_in[3];
    float*       out = (float*)d_out;

    int N = in_sizes[0] / F_IN;   // 100000
    int E = in_sizes[1] / 2;      // 3200000
    int E8 = (E + 7) / 8;

    int g1b   = 2 * ((N + NPB - 1) / NPB);  // 782 split-K gemm1 blocks (first)
    int fillb = (E8 + 255) / 256;           // 1563 fill blocks (backfill)

    k_main    <<<g1b + fillb, 256>>>(x, w1, ei, E, N, g1b);   // overlapped fill+gemm1
    k_finscale<<<(N * 4 + 255) / 256, 256>>>(N);

    int aggw = (N + 1) / 2;                  // warps (2 nodes each)
    k_agg<<<(aggw * 32 + 255) / 256, 256>>>(0, w2, out, N);
    k_agg<<<(aggw * 32 + 255) / 256, 256>>>(1, w2, out, N);
}